// round 6
// baseline (speedup 1.0000x reference)
#include <cuda_runtime.h>

// Hopf oscillator scan — R6: R4 structure (scalar, PF=4, low regs) +
// clamp-free main/epilogue split + 128-thread blocks for wave balance.
// R5 lesson: PF=8 cost occupancy (48 regs) and lost; occupancy dominates.
// Grid 2048x128 => 13.8 blocks/SM, ~7% straggler skew vs 14% at grid 1024.

#define HOPF_DT      0.01f
#define HOPF_SCALER  20.0f

static constexpr int BS  = 8;
static constexpr int T   = 64;
static constexpr int CPB = 32 * 32 * 32;   // channels per batch = 32768
static constexpr int PF  = 4;              // prefetch ring depth (power of 2)

__device__ __forceinline__ float ldcs1(const float* p) {
    float v;
    asm volatile("ld.global.cs.f32 %0, [%1];" : "=f"(v) : "l"(p));
    return v;
}

__device__ __forceinline__ void stcs1(float* p, float v) {
    asm volatile("st.global.cs.f32 [%0], %1;" :: "l"(p), "f"(v) : "memory");
}

__global__ __launch_bounds__(128)
void hopf_scan_kernel(const float* __restrict__ Xr,
                      const float* __restrict__ Xi,
                      const float* __restrict__ Om,
                      float* __restrict__ OutR,
                      float* __restrict__ OutI)
{
    const int u = blockIdx.x * blockDim.x + threadIdx.x;  // 0..262143
    const int b = u >> 15;            // / CPB
    const int c = u & (CPB - 1);      // % CPB

    const float om = Om[c];

    float r = 1.0f, phi = 0.0f, cs = 1.0f, sn = 0.0f;

    const int base = (b * T) * CPB + c;

    // Preload stages t = 0..PF-2
    float xrb[PF], xib[PF];
#pragma unroll
    for (int p = 0; p < PF - 1; ++p) {
        xrb[p] = ldcs1(Xr + base + p * CPB);
        xib[p] = ldcs1(Xi + base + p * CPB);
    }

    // Main loop: prefetch of t+PF-1 always in-bounds (no clamp, no select).
#pragma unroll 4
    for (int t = 0; t < T - (PF - 1); ++t) {
        const int tp = t + PF - 1;
        xrb[tp & (PF - 1)] = ldcs1(Xr + base + tp * CPB);
        xib[tp & (PF - 1)] = ldcs1(Xi + base + tp * CPB);

        const float xr = xrb[t & (PF - 1)];
        const float xi = xib[t & (PF - 1)];

        const float input_r   = HOPF_SCALER * xr * cs;
        const float input_phi = HOPF_SCALER * xi * sn;
        r   = r + ((1.0f - r * r) * r + input_r) * HOPF_DT;
        phi = phi + (om - input_phi) * HOPF_DT;
        __sincosf(phi, &sn, &cs);

        const int off = base + t * CPB;
        stcs1(OutR + off, r * cs);
        stcs1(OutI + off, r * sn);
    }

    // Epilogue: last PF-1 iterations, data already resident in the ring.
#pragma unroll
    for (int t = T - (PF - 1); t < T; ++t) {
        const float xr = xrb[t & (PF - 1)];
        const float xi = xib[t & (PF - 1)];

        const float input_r   = HOPF_SCALER * xr * cs;
        const float input_phi = HOPF_SCALER * xi * sn;
        r   = r + ((1.0f - r * r) * r + input_r) * HOPF_DT;
        phi = phi + (om - input_phi) * HOPF_DT;
        __sincosf(phi, &sn, &cs);

        const int off = base + t * CPB;
        stcs1(OutR + off, r * cs);
        stcs1(OutI + off, r * sn);
    }
}

extern "C" void kernel_launch(void* const* d_in, const int* in_sizes, int n_in,
                              void* d_out, int out_size)
{
    const float* Xr = (const float*)d_in[0];
    const float* Xi = (const float*)d_in[1];
    const float* Om = (const float*)d_in[2];

    float* out  = (float*)d_out;
    const int n_elem = BS * T * CPB;            // 16,777,216 per output tensor
    float* OutR = out;
    float* OutI = out + n_elem;

    const int n_threads = BS * CPB;             // 262144
    hopf_scan_kernel<<<n_threads / 128, 128>>>(Xr, Xi, Om, OutR, OutI);
}

// round 7
// speedup vs baseline: 1.0050x; 1.0050x over previous
#include <cuda_runtime.h>

// Hopf oscillator scan — R7: R4 exactly (scalar, PF=4, 256-thread blocks)
// + ONLY the clamp-free main/epilogue split. R6 confounded this change with
// block=128 (which regressed); this isolates the clamp removal.

#define HOPF_DT      0.01f
#define HOPF_SCALER  20.0f

static constexpr int BS  = 8;
static constexpr int T   = 64;
static constexpr int CPB = 32 * 32 * 32;   // channels per batch = 32768
static constexpr int PF  = 4;              // prefetch ring depth (power of 2)

__device__ __forceinline__ float ldcs1(const float* p) {
    float v;
    asm volatile("ld.global.cs.f32 %0, [%1];" : "=f"(v) : "l"(p));
    return v;
}

__device__ __forceinline__ void stcs1(float* p, float v) {
    asm volatile("st.global.cs.f32 [%0], %1;" :: "l"(p), "f"(v) : "memory");
}

__global__ __launch_bounds__(256)
void hopf_scan_kernel(const float* __restrict__ Xr,
                      const float* __restrict__ Xi,
                      const float* __restrict__ Om,
                      float* __restrict__ OutR,
                      float* __restrict__ OutI)
{
    const int u = blockIdx.x * blockDim.x + threadIdx.x;  // 0..262143
    const int b = u >> 15;            // / CPB
    const int c = u & (CPB - 1);      // % CPB

    const float om = Om[c];

    float r = 1.0f, phi = 0.0f, cs = 1.0f, sn = 0.0f;

    const int base = (b * T) * CPB + c;

    // Preload stages t = 0..PF-2
    float xrb[PF], xib[PF];
#pragma unroll
    for (int p = 0; p < PF - 1; ++p) {
        xrb[p] = ldcs1(Xr + base + p * CPB);
        xib[p] = ldcs1(Xi + base + p * CPB);
    }

    // Main loop: prefetch of t+PF-1 always in-bounds (no clamp, no select).
#pragma unroll 4
    for (int t = 0; t < T - (PF - 1); ++t) {
        const int tp = t + PF - 1;
        xrb[tp & (PF - 1)] = ldcs1(Xr + base + tp * CPB);
        xib[tp & (PF - 1)] = ldcs1(Xi + base + tp * CPB);

        const float xr = xrb[t & (PF - 1)];
        const float xi = xib[t & (PF - 1)];

        const float input_r   = HOPF_SCALER * xr * cs;
        const float input_phi = HOPF_SCALER * xi * sn;
        r   = r + ((1.0f - r * r) * r + input_r) * HOPF_DT;
        phi = phi + (om - input_phi) * HOPF_DT;
        __sincosf(phi, &sn, &cs);

        const int off = base + t * CPB;
        stcs1(OutR + off, r * cs);
        stcs1(OutI + off, r * sn);
    }

    // Epilogue: last PF-1 iterations, data already resident in the ring.
#pragma unroll
    for (int t = T - (PF - 1); t < T; ++t) {
        const float xr = xrb[t & (PF - 1)];
        const float xi = xib[t & (PF - 1)];

        const float input_r   = HOPF_SCALER * xr * cs;
        const float input_phi = HOPF_SCALER * xi * sn;
        r   = r + ((1.0f - r * r) * r + input_r) * HOPF_DT;
        phi = phi + (om - input_phi) * HOPF_DT;
        __sincosf(phi, &sn, &cs);

        const int off = base + t * CPB;
        stcs1(OutR + off, r * cs);
        stcs1(OutI + off, r * sn);
    }
}

extern "C" void kernel_launch(void* const* d_in, const int* in_sizes, int n_in,
                              void* d_out, int out_size)
{
    const float* Xr = (const float*)d_in[0];
    const float* Xi = (const float*)d_in[1];
    const float* Om = (const float*)d_in[2];

    float* out  = (float*)d_out;
    const int n_elem = BS * T * CPB;            // 16,777,216 per output tensor
    float* OutR = out;
    float* OutI = out + n_elem;

    const int n_threads = BS * CPB;             // 262144
    hopf_scan_kernel<<<n_threads / 256, 256>>>(Xr, Xi, Om, OutR, OutI);
}

// round 8
// speedup vs baseline: 1.0560x; 1.0507x over previous
#include <cuda_runtime.h>

// Hopf oscillator scan — R8: R4 structure (scalar, PF=4, 256-thread blocks,
// predicated clamp) but with the t-loop FULLY unrolled (T=64 constant) and
// __launch_bounds__(256, 7) to pin regs <=36 (56 warps/SM).
// The clamp ternary now folds at COMPILE time (t is constant per iteration),
// giving the clamp-free codegen R6/R7's runtime split failed to deliver.

#define HOPF_DT      0.01f
#define HOPF_SCALER  20.0f

static constexpr int BS  = 8;
static constexpr int T   = 64;
static constexpr int CPB = 32 * 32 * 32;   // channels per batch = 32768
static constexpr int PF  = 4;              // prefetch ring depth (power of 2)

__device__ __forceinline__ float ldcs1(const float* p) {
    float v;
    asm volatile("ld.global.cs.f32 %0, [%1];" : "=f"(v) : "l"(p));
    return v;
}

__device__ __forceinline__ void stcs1(float* p, float v) {
    asm volatile("st.global.cs.f32 [%0], %1;" :: "l"(p), "f"(v) : "memory");
}

__global__ __launch_bounds__(256, 7)
void hopf_scan_kernel(const float* __restrict__ Xr,
                      const float* __restrict__ Xi,
                      const float* __restrict__ Om,
                      float* __restrict__ OutR,
                      float* __restrict__ OutI)
{
    const int u = blockIdx.x * blockDim.x + threadIdx.x;  // 0..262143
    const int b = u >> 15;            // / CPB
    const int c = u & (CPB - 1);      // % CPB

    const float om = Om[c];

    float r = 1.0f, phi = 0.0f, cs = 1.0f, sn = 0.0f;

    const int base = (b * T) * CPB + c;

    // Preload stages t = 0..PF-2
    float xrb[PF], xib[PF];
#pragma unroll
    for (int p = 0; p < PF - 1; ++p) {
        xrb[p] = ldcs1(Xr + base + p * CPB);
        xib[p] = ldcs1(Xi + base + p * CPB);
    }

    // Fully unrolled: t is a compile-time constant in every iteration, so the
    // tail clamp folds away, ring indices become registers, and offsets are
    // immediates. No loop-control or index ALU at runtime.
#pragma unroll
    for (int t = 0; t < T; ++t) {
        if (t + PF - 1 < T) {   // compile-time predicate per iteration
            const int tp = t + PF - 1;
            xrb[tp & (PF - 1)] = ldcs1(Xr + base + tp * CPB);
            xib[tp & (PF - 1)] = ldcs1(Xi + base + tp * CPB);
        }

        const float xr = xrb[t & (PF - 1)];
        const float xi = xib[t & (PF - 1)];

        const float input_r   = HOPF_SCALER * xr * cs;
        const float input_phi = HOPF_SCALER * xi * sn;
        r   = r + ((1.0f - r * r) * r + input_r) * HOPF_DT;
        phi = phi + (om - input_phi) * HOPF_DT;
        __sincosf(phi, &sn, &cs);

        const int off = base + t * CPB;
        stcs1(OutR + off, r * cs);
        stcs1(OutI + off, r * sn);
    }
}

extern "C" void kernel_launch(void* const* d_in, const int* in_sizes, int n_in,
                              void* d_out, int out_size)
{
    const float* Xr = (const float*)d_in[0];
    const float* Xi = (const float*)d_in[1];
    const float* Om = (const float*)d_in[2];

    float* out  = (float*)d_out;
    const int n_elem = BS * T * CPB;            // 16,777,216 per output tensor
    float* OutR = out;
    float* OutI = out + n_elem;

    const int n_threads = BS * CPB;             // 262144
    hopf_scan_kernel<<<n_threads / 256, 256>>>(Xr, Xi, Om, OutR, OutI);
}

// round 9
// speedup vs baseline: 1.0608x; 1.0046x over previous
#include <cuda_runtime.h>

// Hopf oscillator scan — R9 (final form): R8 (scalar, PF=4, full unroll,
// launch_bounds(256,7)) with asm-volatile ld/st replaced by __ldcs/__stcs
// intrinsics. asm volatile pinned program order among all memory ops,
// blocking ptxas from hoisting next-iteration loads above the current
// sincos/store chain; intrinsics free the scheduler while keeping the
// streaming (evict-first) cache policy.
//
// Established across R1-R8: kernel is at the HBM mixed-R/W ceiling
// (256 MB compulsory traffic, 6.6 TB/s app throughput, DRAM ~71%,
// occupancy grid-limited). R4 vs R8 proved instruction mix no longer
// moves runtime.

#define HOPF_DT      0.01f
#define HOPF_SCALER  20.0f

static constexpr int BS  = 8;
static constexpr int T   = 64;
static constexpr int CPB = 32 * 32 * 32;   // channels per batch = 32768
static constexpr int PF  = 4;              // prefetch ring depth (power of 2)

__global__ __launch_bounds__(256, 7)
void hopf_scan_kernel(const float* __restrict__ Xr,
                      const float* __restrict__ Xi,
                      const float* __restrict__ Om,
                      float* __restrict__ OutR,
                      float* __restrict__ OutI)
{
    const int u = blockIdx.x * blockDim.x + threadIdx.x;  // 0..262143
    const int b = u >> 15;            // / CPB
    const int c = u & (CPB - 1);      // % CPB

    const float om = Om[c];

    float r = 1.0f, phi = 0.0f, cs = 1.0f, sn = 0.0f;

    const int base = (b * T) * CPB + c;

    // Preload stages t = 0..PF-2
    float xrb[PF], xib[PF];
#pragma unroll
    for (int p = 0; p < PF - 1; ++p) {
        xrb[p] = __ldcs(Xr + base + p * CPB);
        xib[p] = __ldcs(Xi + base + p * CPB);
    }

    // Fully unrolled: t is a compile-time constant per iteration, so the tail
    // predicate folds away, ring slots become registers, offsets become
    // immediates, and the scheduler is free to batch loads ahead of compute.
#pragma unroll
    for (int t = 0; t < T; ++t) {
        if (t + PF - 1 < T) {   // compile-time predicate
            const int tp = t + PF - 1;
            xrb[tp & (PF - 1)] = __ldcs(Xr + base + tp * CPB);
            xib[tp & (PF - 1)] = __ldcs(Xi + base + tp * CPB);
        }

        const float xr = xrb[t & (PF - 1)];
        const float xi = xib[t & (PF - 1)];

        const float input_r   = HOPF_SCALER * xr * cs;
        const float input_phi = HOPF_SCALER * xi * sn;
        r   = r + ((1.0f - r * r) * r + input_r) * HOPF_DT;
        phi = phi + (om - input_phi) * HOPF_DT;
        __sincosf(phi, &sn, &cs);

        const int off = base + t * CPB;
        __stcs(OutR + off, r * cs);
        __stcs(OutI + off, r * sn);
    }
}

extern "C" void kernel_launch(void* const* d_in, const int* in_sizes, int n_in,
                              void* d_out, int out_size)
{
    const float* Xr = (const float*)d_in[0];
    const float* Xi = (const float*)d_in[1];
    const float* Om = (const float*)d_in[2];

    float* out  = (float*)d_out;
    const int n_elem = BS * T * CPB;            // 16,777,216 per output tensor
    float* OutR = out;
    float* OutI = out + n_elem;

    const int n_threads = BS * CPB;             // 262144
    hopf_scan_kernel<<<n_threads / 256, 256>>>(Xr, Xi, Om, OutR, OutI);
}

// round 10
// speedup vs baseline: 1.0907x; 1.0282x over previous
#include <cuda_runtime.h>

// Hopf oscillator scan — R10 (final): R9 with default-policy stores.
// Reads keep .cs (streaming, no L2 pollution of the 128MB read stream);
// stores use default eviction so the 126MB L2 can absorb write bursts and
// drain to DRAM opportunistically instead of competing head-on with reads.
//
// Plateau evidence (R3/R4/R8/R9, four different codegens): kernel time
// 38.8-39.2us = 6.6 TB/s app throughput on 256MB compulsory traffic =
// ~82% of HBM3e spec — the mixed 50/50 R/W ceiling. Occupancy grid-limited
// (79%), all compute pipes <13%, traffic irreducible (nonlinear scan).

#define HOPF_DT      0.01f
#define HOPF_SCALER  20.0f

static constexpr int BS  = 8;
static constexpr int T   = 64;
static constexpr int CPB = 32 * 32 * 32;   // channels per batch = 32768
static constexpr int PF  = 4;              // prefetch ring depth (power of 2)

__global__ __launch_bounds__(256, 7)
void hopf_scan_kernel(const float* __restrict__ Xr,
                      const float* __restrict__ Xi,
                      const float* __restrict__ Om,
                      float* __restrict__ OutR,
                      float* __restrict__ OutI)
{
    const int u = blockIdx.x * blockDim.x + threadIdx.x;  // 0..262143
    const int b = u >> 15;            // / CPB
    const int c = u & (CPB - 1);      // % CPB

    const float om = Om[c];

    float r = 1.0f, phi = 0.0f, cs = 1.0f, sn = 0.0f;

    const int base = (b * T) * CPB + c;

    // Preload stages t = 0..PF-2 (streaming reads)
    float xrb[PF], xib[PF];
#pragma unroll
    for (int p = 0; p < PF - 1; ++p) {
        xrb[p] = __ldcs(Xr + base + p * CPB);
        xib[p] = __ldcs(Xi + base + p * CPB);
    }

    // Fully unrolled: t is a compile-time constant per iteration — the tail
    // predicate folds away, ring slots become registers, offsets become
    // immediates, and ptxas batches loads ahead of the compute chain.
#pragma unroll
    for (int t = 0; t < T; ++t) {
        if (t + PF - 1 < T) {   // compile-time predicate
            const int tp = t + PF - 1;
            xrb[tp & (PF - 1)] = __ldcs(Xr + base + tp * CPB);
            xib[tp & (PF - 1)] = __ldcs(Xi + base + tp * CPB);
        }

        const float xr = xrb[t & (PF - 1)];
        const float xi = xib[t & (PF - 1)];

        const float input_r   = HOPF_SCALER * xr * cs;
        const float input_phi = HOPF_SCALER * xi * sn;
        r   = r + ((1.0f - r * r) * r + input_r) * HOPF_DT;
        phi = phi + (om - input_phi) * HOPF_DT;
        __sincosf(phi, &sn, &cs);

        const int off = base + t * CPB;
        OutR[off] = r * cs;   // default policy: let L2 buffer the write stream
        OutI[off] = r * sn;
    }
}

extern "C" void kernel_launch(void* const* d_in, const int* in_sizes, int n_in,
                              void* d_out, int out_size)
{
    const float* Xr = (const float*)d_in[0];
    const float* Xi = (const float*)d_in[1];
    const float* Om = (const float*)d_in[2];

    float* out  = (float*)d_out;
    const int n_elem = BS * T * CPB;            // 16,777,216 per output tensor
    float* OutR = out;
    float* OutI = out + n_elem;

    const int n_threads = BS * CPB;             // 262144
    hopf_scan_kernel<<<n_threads / 256, 256>>>(Xr, Xi, Om, OutR, OutI);
}